// round 5
// baseline (speedup 1.0000x reference)
#include <cuda_runtime.h>
#include <cuda_bf16.h>
#include <cstdint>
#include <math.h>

#define DM     1024
#define BATCHN 1024
#define HEADS  16
#define DK     64

// ---------------- scratch (no allocation allowed) ----------------
__device__ float g_qkv[3u * BATCHN * DM];            // q | k | v fp32
__device__ float g_beta[BATCHN * HEADS];
__device__ __nv_bfloat16 g_xh[BATCHN * DM];          // x split hi
__device__ __nv_bfloat16 g_xl[BATCHN * DM];          // x split lo
__device__ __nv_bfloat16 g_wth[4u * DM * DM];        // W^T split hi: Wq,Wk,Wv,Wo
__device__ __nv_bfloat16 g_wtl[4u * DM * DM];        // W^T split lo
__device__ __nv_bfloat16 g_ohh[BATCHN * DM];         // outh split hi
__device__ __nv_bfloat16 g_ohl[BATCHN * DM];         // outh split lo

// ---------------------------------------------------------------------------
// split fp32 -> bf16 hi/lo
// ---------------------------------------------------------------------------
__global__ __launch_bounds__(256) void split_kernel(
    const float* __restrict__ in, __nv_bfloat16* __restrict__ hi,
    __nv_bfloat16* __restrict__ lo)
{
    int idx = blockIdx.x * 256 + threadIdx.x;   // float4 index
    float4 v = reinterpret_cast<const float4*>(in)[idx];
    float f[4] = {v.x, v.y, v.z, v.w};
    __nv_bfloat16 h[4], l[4];
#pragma unroll
    for (int i = 0; i < 4; i++) {
        h[i] = __float2bfloat16_rn(f[i]);
        l[i] = __float2bfloat16_rn(f[i] - __bfloat162float(h[i]));
    }
    __nv_bfloat162* h2 = reinterpret_cast<__nv_bfloat162*>(hi);
    __nv_bfloat162* l2 = reinterpret_cast<__nv_bfloat162*>(lo);
    h2[idx * 2 + 0] = __nv_bfloat162(h[0], h[1]);
    h2[idx * 2 + 1] = __nv_bfloat162(h[2], h[3]);
    l2[idx * 2 + 0] = __nv_bfloat162(l[0], l[1]);
    l2[idx * 2 + 1] = __nv_bfloat162(l[2], l[3]);
}

// ---------------------------------------------------------------------------
// transpose + split: W[K][N] -> Wt hi/lo [N][K] bf16. z selects matrix.
// ---------------------------------------------------------------------------
__global__ __launch_bounds__(256) void transsplit_kernel(
    const float* __restrict__ W0, const float* __restrict__ W1,
    const float* __restrict__ W2, const float* __restrict__ W3,
    __nv_bfloat16* __restrict__ hi, __nv_bfloat16* __restrict__ lo)
{
    __shared__ float tile[32][33];
    const int z = blockIdx.z;
    const float* W = (z == 0) ? W0 : (z == 1) ? W1 : (z == 2) ? W2 : W3;
    __nv_bfloat16* H = hi + (size_t)z * DM * DM;
    __nv_bfloat16* L = lo + (size_t)z * DM * DM;
    const int tx = threadIdx.x & 31, ty = threadIdx.x >> 5;
    const int nb = blockIdx.x * 32, kb = blockIdx.y * 32;
#pragma unroll
    for (int i = 0; i < 4; i++) {
        int k = kb + ty + i * 8;
        tile[ty + i * 8][tx] = W[(size_t)k * DM + nb + tx];
    }
    __syncthreads();
#pragma unroll
    for (int i = 0; i < 4; i++) {
        int n = nb + ty + i * 8;
        float v = tile[tx][ty + i * 8];
        __nv_bfloat16 h = __float2bfloat16_rn(v);
        __nv_bfloat16 l = __float2bfloat16_rn(v - __bfloat162float(h));
        H[(size_t)n * DM + kb + tx] = h;
        L[(size_t)n * DM + kb + tx] = l;
    }
}

// ---------------------------------------------------------------------------
// bf16-split GEMM on mma.sync + ldmatrix. C = Ah*Bh + Al*Bh + Ah*Bl.
// CTA tile 128x128, BK=16, 8 warps (2x4), warp tile 64x32,
// 4-stage cp.async pipeline, one barrier per k-iteration.
// ---------------------------------------------------------------------------
#define TSTRIDE   48                    // bytes per 16-bf16 smem row (+16 pad)
#define TILE_B    (128 * TSTRIDE)       // 6144 per operand tile
#define MM_STAGE  (4 * TILE_B)          // Ah | Al | Bh | Bl = 24576
#define MM_SMEM   (4 * MM_STAGE)        // 98304

__device__ __forceinline__ void mma_bf16(float* c, const uint32_t* a, const uint32_t* b) {
    asm volatile(
        "mma.sync.aligned.m16n8k16.row.col.f32.bf16.bf16.f32 "
        "{%0,%1,%2,%3}, {%4,%5,%6,%7}, {%8,%9}, {%0,%1,%2,%3};"
        : "+f"(c[0]), "+f"(c[1]), "+f"(c[2]), "+f"(c[3])
        : "r"(a[0]), "r"(a[1]), "r"(a[2]), "r"(a[3]), "r"(b[0]), "r"(b[1]));
}

__device__ __forceinline__ void ldsm4(uint32_t* r, uint32_t addr) {
    asm volatile("ldmatrix.sync.aligned.m8n8.x4.shared.b16 {%0,%1,%2,%3}, [%4];"
        : "=r"(r[0]), "=r"(r[1]), "=r"(r[2]), "=r"(r[3]) : "r"(addr));
}

__device__ __forceinline__ void cp16(void* s, const void* g) {
    uint32_t sa;
    asm("{ .reg .u64 t; cvta.to.shared.u64 t, %1; cvt.u32.u64 %0, t; }" : "=r"(sa) : "l"(s));
    asm volatile("cp.async.cg.shared.global [%0], [%1], 16;" :: "r"(sa), "l"(g));
}

// one 16B chunk per tile per thread (4 tiles x 256 chunks = 1024 / 256 thr)
__device__ __forceinline__ void cp_stage4(
    char* smStage, const char* aH, const char* aL, const char* bH, const char* bL,
    int ktBytes, int tid)
{
    const int r = tid >> 1, c = tid & 1;
    const size_t goff = ((size_t)r << 11) + (size_t)ktBytes + (c << 4);
    const int soff = r * TSTRIDE + (c << 4);
    cp16(smStage + 0 * TILE_B + soff, aH + goff);
    cp16(smStage + 1 * TILE_B + soff, aL + goff);
    cp16(smStage + 2 * TILE_B + soff, bH + goff);
    cp16(smStage + 3 * TILE_B + soff, bL + goff);
    asm volatile("cp.async.commit_group;");
}

__global__ __launch_bounds__(256, 2) void mm_kernel(
    const __nv_bfloat16* __restrict__ Ah, const __nv_bfloat16* __restrict__ Al,
    const __nv_bfloat16* __restrict__ Bth0, const __nv_bfloat16* __restrict__ Btl0,
    const __nv_bfloat16* __restrict__ Bth1, const __nv_bfloat16* __restrict__ Btl1,
    const __nv_bfloat16* __restrict__ Bth2, const __nv_bfloat16* __restrict__ Btl2,
    float* __restrict__ C0, float* __restrict__ C1, float* __restrict__ C2,
    const float* __restrict__ bias)
{
    extern __shared__ char sm[];
    uint32_t smbase;
    asm("{ .reg .u64 t; cvta.to.shared.u64 t, %1; cvt.u32.u64 %0, t; }"
        : "=r"(smbase) : "l"(sm));

    const int tid = threadIdx.x;
    const int warp = tid >> 5, lane = tid & 31;
    const int g = lane >> 2, tg = lane & 3;
    const int z = blockIdx.z;
    const __nv_bfloat16* Bth = (z == 0) ? Bth0 : (z == 1) ? Bth1 : Bth2;
    const __nv_bfloat16* Btl = (z == 0) ? Btl0 : (z == 1) ? Btl1 : Btl2;
    float* C = (z == 0) ? C0 : (z == 1) ? C1 : C2;

    const int rowBase = blockIdx.y * 128;
    const int colBase = blockIdx.x * 128;
    const int warpRow = (warp & 1) * 64;
    const int warpCol = (warp >> 1) * 32;

    const char* aHp = (const char*)Ah  + ((size_t)rowBase << 11);
    const char* aLp = (const char*)Al  + ((size_t)rowBase << 11);
    const char* bHp = (const char*)Bth + ((size_t)colBase << 11);
    const char* bLp = (const char*)Btl + ((size_t)colBase << 11);

    // per-thread ldmatrix row addresses (relative to stage base)
    // A: mat i (lanes 8i..8i+7): rows 0-7/8-15 at k+0, rows 0-7/8-15 at k+16B
    uint32_t aoffs[4];
#pragma unroll
    for (int mi = 0; mi < 4; mi++)
        aoffs[mi] = (uint32_t)((warpRow + mi * 16 + ((lane >> 3) & 1) * 8 + (lane & 7)) * TSTRIDE
                               + (lane >> 4) * 16);
    // B: mats: cols p*16+0-7 @k0, @k16B, cols p*16+8-15 @k0, @k16B
    uint32_t boffs[2];
#pragma unroll
    for (int p = 0; p < 2; p++)
        boffs[p] = (uint32_t)(2 * TILE_B
                              + (warpCol + p * 16 + (lane >> 4) * 8 + (lane & 7)) * TSTRIDE
                              + ((lane >> 3) & 1) * 16);

    float acc[4][4][4];
#pragma unroll
    for (int mi = 0; mi < 4; mi++)
#pragma unroll
        for (int ni = 0; ni < 4; ni++)
#pragma unroll
            for (int e = 0; e < 4; e++) acc[mi][ni][e] = 0.f;

    // prologue: 3 chunks in flight
    cp_stage4(sm + 0 * MM_STAGE, aHp, aLp, bHp, bLp, 0,  tid);
    cp_stage4(sm + 1 * MM_STAGE, aHp, aLp, bHp, bLp, 32, tid);
    cp_stage4(sm + 2 * MM_STAGE, aHp, aLp, bHp, bLp, 64, tid);

    for (int it = 0; it < 64; it++) {
        if (it < 61)       asm volatile("cp.async.wait_group 2;" ::: "memory");
        else if (it == 61) asm volatile("cp.async.wait_group 1;" ::: "memory");
        else               asm volatile("cp.async.wait_group 0;" ::: "memory");
        __syncthreads();
        if (it + 3 < 64)
            cp_stage4(sm + ((it + 3) & 3) * MM_STAGE, aHp, aLp, bHp, bLp,
                      (it + 3) * 32, tid);

        const uint32_t so = smbase + (it & 3) * MM_STAGE;

        uint32_t ahf[4][4];
#pragma unroll
        for (int mi = 0; mi < 4; mi++) ldsm4(&ahf[mi][0], so + aoffs[mi]);
        uint32_t bhf[4][2];
        ldsm4(&bhf[0][0], so + boffs[0]);
        ldsm4(&bhf[2][0], so + boffs[1]);

        // pass 1: Ah * Bh
#pragma unroll
        for (int mi = 0; mi < 4; mi++)
#pragma unroll
            for (int ni = 0; ni < 4; ni++)
                mma_bf16(acc[mi][ni], ahf[mi], bhf[ni]);
        // pass 2: Al * Bh
        {
            uint32_t alf[4][4];
#pragma unroll
            for (int mi = 0; mi < 4; mi++) ldsm4(&alf[mi][0], so + aoffs[mi] + TILE_B);
#pragma unroll
            for (int mi = 0; mi < 4; mi++)
#pragma unroll
                for (int ni = 0; ni < 4; ni++)
                    mma_bf16(acc[mi][ni], alf[mi], bhf[ni]);
        }
        // pass 3: Ah * Bl
        {
            uint32_t blf[4][2];
            ldsm4(&blf[0][0], so + boffs[0] + TILE_B);
            ldsm4(&blf[2][0], so + boffs[1] + TILE_B);
#pragma unroll
            for (int mi = 0; mi < 4; mi++)
#pragma unroll
                for (int ni = 0; ni < 4; ni++)
                    mma_bf16(acc[mi][ni], ahf[mi], blf[ni]);
        }
    }

    // epilogue: direct float2 stores
#pragma unroll
    for (int mi = 0; mi < 4; mi++) {
        const int row0 = rowBase + warpRow + mi * 16 + g;
#pragma unroll
        for (int ni = 0; ni < 4; ni++) {
            const int col = colBase + warpCol + ni * 8 + tg * 2;
            float b0 = 0.f, b1 = 0.f;
            if (bias) { b0 = bias[col]; b1 = bias[col + 1]; }
            float2 v0 = make_float2(acc[mi][ni][0] + b0, acc[mi][ni][1] + b1);
            float2 v1 = make_float2(acc[mi][ni][2] + b0, acc[mi][ni][3] + b1);
            *reinterpret_cast<float2*>(&C[(size_t)row0 * DM + col]) = v0;
            *reinterpret_cast<float2*>(&C[(size_t)(row0 + 8) * DM + col]) = v1;
        }
    }
}

// ---------------------------------------------------------------------------
// beta = sigmoid(x @ Wg)
// ---------------------------------------------------------------------------
__global__ __launch_bounds__(512) void beta_kernel(
    const float* __restrict__ x, const float* __restrict__ Wg,
    float* __restrict__ beta)
{
    __shared__ float xs[DM];
    const int b = blockIdx.x;
    for (int i = threadIdx.x; i < DM; i += 512) xs[i] = x[(size_t)b * DM + i];
    __syncthreads();
    const int w = threadIdx.x >> 5, lane = threadIdx.x & 31;
    float s = 0.f;
    for (int j = lane; j < DM; j += 32) s = fmaf(xs[j], Wg[(size_t)j * HEADS + w], s);
#pragma unroll
    for (int off = 16; off; off >>= 1) s += __shfl_xor_sync(0xffffffffu, s, off);
    if (lane == 0) beta[b * HEADS + w] = 1.f / (1.f + expf(-s));
}

// ---------------------------------------------------------------------------
// fast-weight delta rule, one 64-thread CTA per (b,h).
// Emits per-head output pre-split to bf16 hi/lo (feeds Wo GEMM directly).
// ---------------------------------------------------------------------------
__global__ __launch_bounds__(64) void fastweight_kernel(
    const float* __restrict__ weights,
    const float* __restrict__ q, const float* __restrict__ k,
    const float* __restrict__ v, const float* __restrict__ beta,
    float* __restrict__ nw,
    __nv_bfloat16* __restrict__ ohh, __nv_bfloat16* __restrict__ ohl)
{
    __shared__ float Wsh[DK][DK + 1];
    __shared__ float ksh[DK], qsh[DK], dsh[DK];

    const int bh = blockIdx.x;
    const int b = bh >> 4, h = bh & 15;
    const int t = threadIdx.x;

    const float4* W4 = reinterpret_cast<const float4*>(weights + (size_t)bh * (DK * DK));
#pragma unroll
    for (int i = 0; i < 16; i++) {
        int id = t + i * 64;
        float4 wv = W4[id];
        int e = id << 2;
        int r = e >> 6, c = e & 63;
        Wsh[r][c + 0] = wv.x; Wsh[r][c + 1] = wv.y;
        Wsh[r][c + 2] = wv.z; Wsh[r][c + 3] = wv.w;
    }
    const size_t base = (size_t)b * DM + (size_t)h * DK;
    const float kval = k[base + t];
    const float qval = q[base + t];
    const float vval = v[base + t];
    ksh[t] = kval; qsh[t] = qval;
    const float betav = beta[bh];
    __syncthreads();

    float s = 0.f;
#pragma unroll
    for (int j = 0; j < DK; j++) s = fmaf(Wsh[t][j], ksh[j], s);
    const float dv = betav * (vval - s);
    dsh[t] = dv;
    __syncthreads();

    float s2 = 0.f, kq = 0.f;
#pragma unroll
    for (int j = 0; j < DK; j++) {
        s2 = fmaf(Wsh[t][j], qsh[j], s2);
        kq = fmaf(ksh[j], qsh[j], kq);
    }
    const float o = s2 + dv * kq;
    const __nv_bfloat16 oh = __float2bfloat16_rn(o);
    ohh[base + t] = oh;
    ohl[base + t] = __float2bfloat16_rn(o - __bfloat162float(oh));

    float* NW = nw + (size_t)bh * (DK * DK);
    const int r0 = t >> 4, c4 = (t & 15) << 2;
    float4 k4;
    k4.x = ksh[c4 + 0]; k4.y = ksh[c4 + 1]; k4.z = ksh[c4 + 2]; k4.w = ksh[c4 + 3];
#pragma unroll
    for (int vr = 0; vr < DK; vr += 4) {
        const int row = vr + r0;
        const float d = dsh[row];
        float4 o4;
        o4.x = Wsh[row][c4 + 0] + d * k4.x;
        o4.y = Wsh[row][c4 + 1] + d * k4.y;
        o4.z = Wsh[row][c4 + 2] + d * k4.z;
        o4.w = Wsh[row][c4 + 3] + d * k4.w;
        *reinterpret_cast<float4*>(&NW[row * DK + c4]) = o4;
    }
}

// ---------------------------------------------------------------------------
extern "C" void kernel_launch(void* const* d_in, const int* in_sizes, int n_in,
                              void* d_out, int out_size)
{
    const float* x       = (const float*)d_in[0];
    const float* weights = (const float*)d_in[1];
    const float* Wq      = (const float*)d_in[2];
    const float* Wk      = (const float*)d_in[3];
    const float* Wv      = (const float*)d_in[4];
    const float* Wg      = (const float*)d_in[5];
    const float* Wo      = (const float*)d_in[6];
    const float* bo      = (const float*)d_in[7];

    float* out = (float*)d_out;
    float* nw  = out + (size_t)BATCHN * DM;

    float *qb, *bb;
    __nv_bfloat16 *xh, *xl, *wth, *wtl, *ohh, *ohl;
    cudaGetSymbolAddress((void**)&qb,  g_qkv);
    cudaGetSymbolAddress((void**)&bb,  g_beta);
    cudaGetSymbolAddress((void**)&xh,  g_xh);
    cudaGetSymbolAddress((void**)&xl,  g_xl);
    cudaGetSymbolAddress((void**)&wth, g_wth);
    cudaGetSymbolAddress((void**)&wtl, g_wtl);
    cudaGetSymbolAddress((void**)&ohh, g_ohh);
    cudaGetSymbolAddress((void**)&ohl, g_ohl);
    float* kb = qb + (size_t)BATCHN * DM;
    float* vb = kb + (size_t)BATCHN * DM;

    cudaFuncSetAttribute(mm_kernel, cudaFuncAttributeMaxDynamicSharedMemorySize, MM_SMEM);

    const size_t MS = (size_t)DM * DM;

    // 1) transpose + bf16-split the four big weight matrices
    transsplit_kernel<<<dim3(32, 32, 4), 256>>>(Wq, Wk, Wv, Wo, wth, wtl);
    // 2) split x
    split_kernel<<<1024, 256>>>(x, xh, xl);
    // 3) gate
    beta_kernel<<<BATCHN, 512>>>(x, Wg, bb);
    // 4) QKV projections (fused, grid.z = 3)
    mm_kernel<<<dim3(8, 8, 3), 256, MM_SMEM>>>(
        xh, xl,
        wth + 0 * MS, wtl + 0 * MS,
        wth + 1 * MS, wtl + 1 * MS,
        wth + 2 * MS, wtl + 2 * MS,
        qb, kb, vb, nullptr);
    // 5) fast-weight update + read (writes nw into d_out, outh pre-split bf16)
    fastweight_kernel<<<BATCHN * HEADS, 64>>>(weights, qb, kb, vb, bb, nw, ohh, ohl);
    // 6) output projection + bias
    mm_kernel<<<dim3(8, 8, 1), 256, MM_SMEM>>>(
        ohh, ohl,
        wth + 3 * MS, wtl + 3 * MS,
        wth + 3 * MS, wtl + 3 * MS,
        wth + 3 * MS, wtl + 3 * MS,
        out, out, out, bo);
}

// round 6
// speedup vs baseline: 1.0584x; 1.0584x over previous
#include <cuda_runtime.h>
#include <cuda_bf16.h>
#include <cstdint>
#include <math.h>

#define DM     1024
#define BATCHN 1024
#define HEADS  16
#define DK     64

// ---------------- scratch (no allocation allowed) ----------------
__device__ float g_qkv[3u * BATCHN * DM];            // q | k | v fp32
__device__ float g_beta[BATCHN * HEADS];
__device__ __nv_bfloat16 g_xh[BATCHN * DM];          // x split hi
__device__ __nv_bfloat16 g_xl[BATCHN * DM];          // x split lo
__device__ __nv_bfloat16 g_wth[4u * DM * DM];        // W^T split hi: Wq,Wk,Wv,Wo
__device__ __nv_bfloat16 g_wtl[4u * DM * DM];        // W^T split lo
__device__ __nv_bfloat16 g_ohh[BATCHN * DM];         // outh split hi
__device__ __nv_bfloat16 g_ohl[BATCHN * DM];         // outh split lo

// ---------------------------------------------------------------------------
// split fp32 -> bf16 hi/lo
// ---------------------------------------------------------------------------
__global__ __launch_bounds__(256) void split_kernel(
    const float* __restrict__ in, __nv_bfloat16* __restrict__ hi,
    __nv_bfloat16* __restrict__ lo)
{
    int idx = blockIdx.x * 256 + threadIdx.x;   // float4 index
    float4 v = reinterpret_cast<const float4*>(in)[idx];
    float f[4] = {v.x, v.y, v.z, v.w};
    __nv_bfloat16 h[4], l[4];
#pragma unroll
    for (int i = 0; i < 4; i++) {
        h[i] = __float2bfloat16_rn(f[i]);
        l[i] = __float2bfloat16_rn(f[i] - __bfloat162float(h[i]));
    }
    __nv_bfloat162* h2 = reinterpret_cast<__nv_bfloat162*>(hi);
    __nv_bfloat162* l2 = reinterpret_cast<__nv_bfloat162*>(lo);
    h2[idx * 2 + 0] = __nv_bfloat162(h[0], h[1]);
    h2[idx * 2 + 1] = __nv_bfloat162(h[2], h[3]);
    l2[idx * 2 + 0] = __nv_bfloat162(l[0], l[1]);
    l2[idx * 2 + 1] = __nv_bfloat162(l[2], l[3]);
}

// ---------------------------------------------------------------------------
// transpose + split: W[K][N] -> Wt hi/lo [N][K] bf16. z selects matrix.
// ---------------------------------------------------------------------------
__global__ __launch_bounds__(256) void transsplit_kernel(
    const float* __restrict__ W0, const float* __restrict__ W1,
    const float* __restrict__ W2, const float* __restrict__ W3,
    __nv_bfloat16* __restrict__ hi, __nv_bfloat16* __restrict__ lo)
{
    __shared__ float tile[32][33];
    const int z = blockIdx.z;
    const float* W = (z == 0) ? W0 : (z == 1) ? W1 : (z == 2) ? W2 : W3;
    __nv_bfloat16* H = hi + (size_t)z * DM * DM;
    __nv_bfloat16* L = lo + (size_t)z * DM * DM;
    const int tx = threadIdx.x & 31, ty = threadIdx.x >> 5;
    const int nb = blockIdx.x * 32, kb = blockIdx.y * 32;
#pragma unroll
    for (int i = 0; i < 4; i++) {
        int k = kb + ty + i * 8;
        tile[ty + i * 8][tx] = W[(size_t)k * DM + nb + tx];
    }
    __syncthreads();
#pragma unroll
    for (int i = 0; i < 4; i++) {
        int n = nb + ty + i * 8;
        float v = tile[tx][ty + i * 8];
        __nv_bfloat16 h = __float2bfloat16_rn(v);
        __nv_bfloat16 l = __float2bfloat16_rn(v - __bfloat162float(h));
        H[(size_t)n * DM + kb + tx] = h;
        L[(size_t)n * DM + kb + tx] = l;
    }
}

// ---------------------------------------------------------------------------
// bf16-split GEMM on mma.sync. C = Ah*Bh + Al*Bh + Ah*Bl.
// CTA tile 128x128, BK=32, 8 warps (2x4), warp tile 64x32.
// 3-stage cp.async pipeline, XOR-swizzled 64B rows, ONE barrier / iteration.
// ---------------------------------------------------------------------------
#define TILE_B    (128 * 64)            // 8192 bytes per operand tile
#define MM_STAGE  (4 * TILE_B)          // Ah | Al | Bh | Bl = 32768
#define MM_SMEM   (3 * MM_STAGE)        // 98304

__device__ __forceinline__ void mma_bf16(float* c, const uint32_t* a, const uint32_t* b) {
    asm volatile(
        "mma.sync.aligned.m16n8k16.row.col.f32.bf16.bf16.f32 "
        "{%0,%1,%2,%3}, {%4,%5,%6,%7}, {%8,%9}, {%0,%1,%2,%3};"
        : "+f"(c[0]), "+f"(c[1]), "+f"(c[2]), "+f"(c[3])
        : "r"(a[0]), "r"(a[1]), "r"(a[2]), "r"(a[3]), "r"(b[0]), "r"(b[1]));
}

__device__ __forceinline__ void cp16(uint32_t s, const void* g) {
    asm volatile("cp.async.cg.shared.global [%0], [%1], 16;" :: "r"(s), "l"(g));
}

// One stage: 4 tiles x 128 rows x 64B. Thread t -> row t>>1, chunks (t&1)*2,+1.
// smem chunk is XOR-swizzled: phys = c ^ ((r>>1)&3).
__device__ __forceinline__ void cp_stage(
    uint32_t smStage, const char* aH, const char* aL, const char* bH, const char* bL,
    int ktBytes, int tid)
{
    const int r = tid >> 1;
    const int sw = (r >> 1) & 3;
    const char* srcs[4] = {aH, aL, bH, bL};
#pragma unroll
    for (int cc = 0; cc < 2; cc++) {
        const int c = (tid & 1) * 2 + cc;
        const size_t goff = ((size_t)r << 11) + (size_t)ktBytes + (c << 4);
        const uint32_t soff = r * 64 + ((c ^ sw) << 4);
#pragma unroll
        for (int tile = 0; tile < 4; tile++)
            cp16(smStage + tile * TILE_B + soff, srcs[tile] + goff);
    }
    asm volatile("cp.async.commit_group;");
}

__global__ __launch_bounds__(256, 2) void mm_kernel(
    const __nv_bfloat16* __restrict__ Ah, const __nv_bfloat16* __restrict__ Al,
    const __nv_bfloat16* __restrict__ Bth0, const __nv_bfloat16* __restrict__ Btl0,
    const __nv_bfloat16* __restrict__ Bth1, const __nv_bfloat16* __restrict__ Btl1,
    const __nv_bfloat16* __restrict__ Bth2, const __nv_bfloat16* __restrict__ Btl2,
    float* __restrict__ C0, float* __restrict__ C1, float* __restrict__ C2,
    const float* __restrict__ bias)
{
    extern __shared__ char sm[];
    uint32_t smbase;
    asm("{ .reg .u64 t; cvta.to.shared.u64 t, %1; cvt.u32.u64 %0, t; }"
        : "=r"(smbase) : "l"(sm));

    const int tid = threadIdx.x;
    const int warp = tid >> 5, lane = tid & 31;
    const int g = lane >> 2, tg = lane & 3;
    const int z = blockIdx.z;
    const __nv_bfloat16* Bth = (z == 0) ? Bth0 : (z == 1) ? Bth1 : Bth2;
    const __nv_bfloat16* Btl = (z == 0) ? Btl0 : (z == 1) ? Btl1 : Btl2;
    float* C = (z == 0) ? C0 : (z == 1) ? C1 : C2;

    const int rowBase = blockIdx.y * 128;
    const int colBase = blockIdx.x * 128;
    const int warpRow = (warp & 1) * 64;
    const int warpCol = (warp >> 1) * 32;

    const char* aHp = (const char*)Ah  + ((size_t)rowBase << 11);
    const char* aLp = (const char*)Al  + ((size_t)rowBase << 11);
    const char* bHp = (const char*)Bth + ((size_t)colBase << 11);
    const char* bLp = (const char*)Btl + ((size_t)colBase << 11);

    // per-lane swizzle constant (row bits 1-2 come from g for every fragment row)
    const uint32_t sig = (uint32_t)(g & 6) << 3;          // in {0,16,32,48}
    // physical k-offsets for (ks, +0/+16B)
    const uint32_t kp[2][2] = { { (0u ^ sig),  (16u ^ sig) },
                                { (32u ^ sig), (48u ^ sig) } };
    // per-lane row bases (relative to stage start)
    uint32_t aBase[4], bBase[4];
#pragma unroll
    for (int mi = 0; mi < 4; mi++)
        aBase[mi] = (uint32_t)((warpRow + mi * 16 + g) * 64 + tg * 4);
#pragma unroll
    for (int ni = 0; ni < 4; ni++)
        bBase[ni] = (uint32_t)(2 * TILE_B + (warpCol + ni * 8 + g) * 64 + tg * 4);

    float acc[4][4][4];
#pragma unroll
    for (int mi = 0; mi < 4; mi++)
#pragma unroll
        for (int ni = 0; ni < 4; ni++)
#pragma unroll
            for (int e = 0; e < 4; e++) acc[mi][ni][e] = 0.f;

    // prologue: 2 stages in flight
    cp_stage(smbase + 0 * MM_STAGE, aHp, aLp, bHp, bLp, 0,  tid);
    cp_stage(smbase + 1 * MM_STAGE, aHp, aLp, bHp, bLp, 64, tid);

    int buf = 0;
    for (int it = 0; it < 32; it++) {
        if (it == 31) asm volatile("cp.async.wait_group 0;" ::: "memory");
        else          asm volatile("cp.async.wait_group 1;" ::: "memory");
        __syncthreads();
        if (it + 2 < 32) {
            int nb = buf + 2; if (nb >= 3) nb -= 3;
            cp_stage(smbase + nb * MM_STAGE, aHp, aLp, bHp, bLp, (it + 2) * 64, tid);
        }
        const uint32_t so = smbase + buf * MM_STAGE;
        if (++buf == 3) buf = 0;

#pragma unroll
        for (int ks = 0; ks < 2; ks++) {
            const uint32_t k0 = kp[ks][0], k1 = kp[ks][1];
            uint32_t ahf[4][4];
#pragma unroll
            for (int mi = 0; mi < 4; mi++) {
                const uint32_t p0 = so + aBase[mi];
                ahf[mi][0] = *(const uint32_t*)__cvta_shared_to_generic(p0 + k0);
                ahf[mi][1] = *(const uint32_t*)__cvta_shared_to_generic(p0 + k0 + 512);
                ahf[mi][2] = *(const uint32_t*)__cvta_shared_to_generic(p0 + k1);
                ahf[mi][3] = *(const uint32_t*)__cvta_shared_to_generic(p0 + k1 + 512);
            }
            uint32_t bhf[4][2];
#pragma unroll
            for (int ni = 0; ni < 4; ni++) {
                const uint32_t p0 = so + bBase[ni];
                bhf[ni][0] = *(const uint32_t*)__cvta_shared_to_generic(p0 + k0);
                bhf[ni][1] = *(const uint32_t*)__cvta_shared_to_generic(p0 + k1);
            }
            // pass 1: Ah * Bh
#pragma unroll
            for (int mi = 0; mi < 4; mi++)
#pragma unroll
                for (int ni = 0; ni < 4; ni++)
                    mma_bf16(acc[mi][ni], ahf[mi], bhf[ni]);
            // pass 2: Al * Bh
            {
                uint32_t alf[4][4];
#pragma unroll
                for (int mi = 0; mi < 4; mi++) {
                    const uint32_t p0 = so + aBase[mi] + TILE_B;
                    alf[mi][0] = *(const uint32_t*)__cvta_shared_to_generic(p0 + k0);
                    alf[mi][1] = *(const uint32_t*)__cvta_shared_to_generic(p0 + k0 + 512);
                    alf[mi][2] = *(const uint32_t*)__cvta_shared_to_generic(p0 + k1);
                    alf[mi][3] = *(const uint32_t*)__cvta_shared_to_generic(p0 + k1 + 512);
                }
#pragma unroll
                for (int mi = 0; mi < 4; mi++)
#pragma unroll
                    for (int ni = 0; ni < 4; ni++)
                        mma_bf16(acc[mi][ni], alf[mi], bhf[ni]);
            }
            // pass 3: Ah * Bl
            {
                uint32_t blf[4][2];
#pragma unroll
                for (int ni = 0; ni < 4; ni++) {
                    const uint32_t p0 = so + bBase[ni] + TILE_B;
                    blf[ni][0] = *(const uint32_t*)__cvta_shared_to_generic(p0 + k0);
                    blf[ni][1] = *(const uint32_t*)__cvta_shared_to_generic(p0 + k1);
                }
#pragma unroll
                for (int mi = 0; mi < 4; mi++)
#pragma unroll
                    for (int ni = 0; ni < 4; ni++)
                        mma_bf16(acc[mi][ni], ahf[mi], blf[ni]);
            }
        }
    }

    // epilogue: direct float2 stores
#pragma unroll
    for (int mi = 0; mi < 4; mi++) {
        const int row0 = rowBase + warpRow + mi * 16 + g;
#pragma unroll
        for (int ni = 0; ni < 4; ni++) {
            const int col = colBase + warpCol + ni * 8 + tg * 2;
            float b0 = 0.f, b1 = 0.f;
            if (bias) { b0 = bias[col]; b1 = bias[col + 1]; }
            float2 v0 = make_float2(acc[mi][ni][0] + b0, acc[mi][ni][1] + b1);
            float2 v1 = make_float2(acc[mi][ni][2] + b0, acc[mi][ni][3] + b1);
            *reinterpret_cast<float2*>(&C[(size_t)row0 * DM + col]) = v0;
            *reinterpret_cast<float2*>(&C[(size_t)(row0 + 8) * DM + col]) = v1;
        }
    }
}

// ---------------------------------------------------------------------------
// beta = sigmoid(x @ Wg)
// ---------------------------------------------------------------------------
__global__ __launch_bounds__(512) void beta_kernel(
    const float* __restrict__ x, const float* __restrict__ Wg,
    float* __restrict__ beta)
{
    __shared__ float xs[DM];
    const int b = blockIdx.x;
    for (int i = threadIdx.x; i < DM; i += 512) xs[i] = x[(size_t)b * DM + i];
    __syncthreads();
    const int w = threadIdx.x >> 5, lane = threadIdx.x & 31;
    float s = 0.f;
    for (int j = lane; j < DM; j += 32) s = fmaf(xs[j], Wg[(size_t)j * HEADS + w], s);
#pragma unroll
    for (int off = 16; off; off >>= 1) s += __shfl_xor_sync(0xffffffffu, s, off);
    if (lane == 0) beta[b * HEADS + w] = 1.f / (1.f + expf(-s));
}

// ---------------------------------------------------------------------------
// fast-weight delta rule, one 64-thread CTA per (b,h).
// Emits per-head output pre-split to bf16 hi/lo (feeds Wo GEMM directly).
// ---------------------------------------------------------------------------
__global__ __launch_bounds__(64) void fastweight_kernel(
    const float* __restrict__ weights,
    const float* __restrict__ q, const float* __restrict__ k,
    const float* __restrict__ v, const float* __restrict__ beta,
    float* __restrict__ nw,
    __nv_bfloat16* __restrict__ ohh, __nv_bfloat16* __restrict__ ohl)
{
    __shared__ float Wsh[DK][DK + 1];
    __shared__ float ksh[DK], qsh[DK], dsh[DK];

    const int bh = blockIdx.x;
    const int b = bh >> 4, h = bh & 15;
    const int t = threadIdx.x;

    const float4* W4 = reinterpret_cast<const float4*>(weights + (size_t)bh * (DK * DK));
#pragma unroll
    for (int i = 0; i < 16; i++) {
        int id = t + i * 64;
        float4 wv = W4[id];
        int e = id << 2;
        int r = e >> 6, c = e & 63;
        Wsh[r][c + 0] = wv.x; Wsh[r][c + 1] = wv.y;
        Wsh[r][c + 2] = wv.z; Wsh[r][c + 3] = wv.w;
    }
    const size_t base = (size_t)b * DM + (size_t)h * DK;
    const float kval = k[base + t];
    const float qval = q[base + t];
    const float vval = v[base + t];
    ksh[t] = kval; qsh[t] = qval;
    const float betav = beta[bh];
    __syncthreads();

    float s = 0.f;
#pragma unroll
    for (int j = 0; j < DK; j++) s = fmaf(Wsh[t][j], ksh[j], s);
    const float dv = betav * (vval - s);
    dsh[t] = dv;
    __syncthreads();

    float s2 = 0.f, kq = 0.f;
#pragma unroll
    for (int j = 0; j < DK; j++) {
        s2 = fmaf(Wsh[t][j], qsh[j], s2);
        kq = fmaf(ksh[j], qsh[j], kq);
    }
    const float o = s2 + dv * kq;
    const __nv_bfloat16 oh = __float2bfloat16_rn(o);
    ohh[base + t] = oh;
    ohl[base + t] = __float2bfloat16_rn(o - __bfloat162float(oh));

    float* NW = nw + (size_t)bh * (DK * DK);
    const int r0 = t >> 4, c4 = (t & 15) << 2;
    float4 k4;
    k4.x = ksh[c4 + 0]; k4.y = ksh[c4 + 1]; k4.z = ksh[c4 + 2]; k4.w = ksh[c4 + 3];
#pragma unroll
    for (int vr = 0; vr < DK; vr += 4) {
        const int row = vr + r0;
        const float d = dsh[row];
        float4 o4;
        o4.x = Wsh[row][c4 + 0] + d * k4.x;
        o4.y = Wsh[row][c4 + 1] + d * k4.y;
        o4.z = Wsh[row][c4 + 2] + d * k4.z;
        o4.w = Wsh[row][c4 + 3] + d * k4.w;
        *reinterpret_cast<float4*>(&NW[row * DK + c4]) = o4;
    }
}

// ---------------------------------------------------------------------------
extern "C" void kernel_launch(void* const* d_in, const int* in_sizes, int n_in,
                              void* d_out, int out_size)
{
    const float* x       = (const float*)d_in[0];
    const float* weights = (const float*)d_in[1];
    const float* Wq      = (const float*)d_in[2];
    const float* Wk      = (const float*)d_in[3];
    const float* Wv      = (const float*)d_in[4];
    const float* Wg      = (const float*)d_in[5];
    const float* Wo      = (const float*)d_in[6];
    const float* bo      = (const float*)d_in[7];

    float* out = (float*)d_out;
    float* nw  = out + (size_t)BATCHN * DM;

    float *qb, *bb;
    __nv_bfloat16 *xh, *xl, *wth, *wtl, *ohh, *ohl;
    cudaGetSymbolAddress((void**)&qb,  g_qkv);
    cudaGetSymbolAddress((void**)&bb,  g_beta);
    cudaGetSymbolAddress((void**)&xh,  g_xh);
    cudaGetSymbolAddress((void**)&xl,  g_xl);
    cudaGetSymbolAddress((void**)&wth, g_wth);
    cudaGetSymbolAddress((void**)&wtl, g_wtl);
    cudaGetSymbolAddress((void**)&ohh, g_ohh);
    cudaGetSymbolAddress((void**)&ohl, g_ohl);
    float* kb = qb + (size_t)BATCHN * DM;
    float* vb = kb + (size_t)BATCHN * DM;

    cudaFuncSetAttribute(mm_kernel, cudaFuncAttributeMaxDynamicSharedMemorySize, MM_SMEM);

    const size_t MS = (size_t)DM * DM;

    // 1) transpose + bf16-split the four big weight matrices
    transsplit_kernel<<<dim3(32, 32, 4), 256>>>(Wq, Wk, Wv, Wo, wth, wtl);
    // 2) split x
    split_kernel<<<1024, 256>>>(x, xh, xl);
    // 3) gate
    beta_kernel<<<BATCHN, 512>>>(x, Wg, bb);
    // 4) QKV projections (fused, grid.z = 3)
    mm_kernel<<<dim3(8, 8, 3), 256, MM_SMEM>>>(
        xh, xl,
        wth + 0 * MS, wtl + 0 * MS,
        wth + 1 * MS, wtl + 1 * MS,
        wth + 2 * MS, wtl + 2 * MS,
        qb, kb, vb, nullptr);
    // 5) fast-weight update + read (nw -> d_out, outh pre-split bf16)
    fastweight_kernel<<<BATCHN * HEADS, 64>>>(weights, qb, kb, vb, bb, nw, ohh, ohl);
    // 6) output projection + bias
    mm_kernel<<<dim3(8, 8, 1), 256, MM_SMEM>>>(
        ohh, ohl,
        wth + 3 * MS, wtl + 3 * MS,
        wth + 3 * MS, wtl + 3 * MS,
        wth + 3 * MS, wtl + 3 * MS,
        out, out, out, bo);
}

// round 7
// speedup vs baseline: 1.2827x; 1.2119x over previous
#include <cuda_runtime.h>
#include <cuda_bf16.h>
#include <cstdint>
#include <math.h>

#define DM     1024
#define BATCHN 1024
#define HEADS  16
#define DK     64

// ---------------- scratch (no allocation allowed) ----------------
__device__ float g_qkv[3u * BATCHN * DM];            // q | k | v fp32
__device__ float g_beta[BATCHN * HEADS];
__device__ __nv_bfloat16 g_xh[BATCHN * DM];          // x split hi
__device__ __nv_bfloat16 g_xl[BATCHN * DM];          // x split lo
__device__ __nv_bfloat16 g_wth[4u * DM * DM];        // W^T split hi: Wq,Wk,Wv,Wo
__device__ __nv_bfloat16 g_wtl[4u * DM * DM];        // W^T split lo
__device__ __nv_bfloat16 g_ohh[BATCHN * DM];         // outh split hi
__device__ __nv_bfloat16 g_ohl[BATCHN * DM];         // outh split lo

// ---------------------------------------------------------------------------
// split fp32 -> bf16 hi/lo
// ---------------------------------------------------------------------------
__global__ __launch_bounds__(256) void split_kernel(
    const float* __restrict__ in, __nv_bfloat16* __restrict__ hi,
    __nv_bfloat16* __restrict__ lo)
{
    int idx = blockIdx.x * 256 + threadIdx.x;   // float4 index
    float4 v = reinterpret_cast<const float4*>(in)[idx];
    float f[4] = {v.x, v.y, v.z, v.w};
    __nv_bfloat16 h[4], l[4];
#pragma unroll
    for (int i = 0; i < 4; i++) {
        h[i] = __float2bfloat16_rn(f[i]);
        l[i] = __float2bfloat16_rn(f[i] - __bfloat162float(h[i]));
    }
    __nv_bfloat162* h2 = reinterpret_cast<__nv_bfloat162*>(hi);
    __nv_bfloat162* l2 = reinterpret_cast<__nv_bfloat162*>(lo);
    h2[idx * 2 + 0] = __nv_bfloat162(h[0], h[1]);
    h2[idx * 2 + 1] = __nv_bfloat162(h[2], h[3]);
    l2[idx * 2 + 0] = __nv_bfloat162(l[0], l[1]);
    l2[idx * 2 + 1] = __nv_bfloat162(l[2], l[3]);
}

// ---------------------------------------------------------------------------
// transpose + split: W[K][N] -> Wt hi/lo [N][K] bf16. z selects matrix.
// ---------------------------------------------------------------------------
__global__ __launch_bounds__(256) void transsplit_kernel(
    const float* __restrict__ W0, const float* __restrict__ W1,
    const float* __restrict__ W2, const float* __restrict__ W3,
    __nv_bfloat16* __restrict__ hi, __nv_bfloat16* __restrict__ lo)
{
    __shared__ float tile[32][33];
    const int z = blockIdx.z;
    const float* W = (z == 0) ? W0 : (z == 1) ? W1 : (z == 2) ? W2 : W3;
    __nv_bfloat16* H = hi + (size_t)z * DM * DM;
    __nv_bfloat16* L = lo + (size_t)z * DM * DM;
    const int tx = threadIdx.x & 31, ty = threadIdx.x >> 5;
    const int nb = blockIdx.x * 32, kb = blockIdx.y * 32;
#pragma unroll
    for (int i = 0; i < 4; i++) {
        int k = kb + ty + i * 8;
        tile[ty + i * 8][tx] = W[(size_t)k * DM + nb + tx];
    }
    __syncthreads();
#pragma unroll
    for (int i = 0; i < 4; i++) {
        int n = nb + ty + i * 8;
        float v = tile[tx][ty + i * 8];
        __nv_bfloat16 h = __float2bfloat16_rn(v);
        __nv_bfloat16 l = __float2bfloat16_rn(v - __bfloat162float(h));
        H[(size_t)n * DM + kb + tx] = h;
        L[(size_t)n * DM + kb + tx] = l;
    }
}

// ---------------------------------------------------------------------------
// bf16-split GEMM on mma.sync. C = Ah*Bh + Al*Bh + Ah*Bl.
// CTA tile 64x128, BK=32, 8 warps (2x4), warp tile 32x32.
// 3-stage cp.async pipeline, XOR-swizzled 64B rows, one barrier / iteration.
// 3 CTAs/SM target (smem 72KB, regs capped at 85).
// ---------------------------------------------------------------------------
#define A_TILE    4096                  // 64 rows x 64B
#define B_TILE    8192                  // 128 rows x 64B
#define OFF_AH    0
#define OFF_AL    4096
#define OFF_BH    8192
#define OFF_BL    16384
#define MM_STAGE  24576
#define MM_SMEM   (3 * MM_STAGE)        // 73728

__device__ __forceinline__ void mma_bf16(float* c, const uint32_t* a, const uint32_t* b) {
    asm volatile(
        "mma.sync.aligned.m16n8k16.row.col.f32.bf16.bf16.f32 "
        "{%0,%1,%2,%3}, {%4,%5,%6,%7}, {%8,%9}, {%0,%1,%2,%3};"
        : "+f"(c[0]), "+f"(c[1]), "+f"(c[2]), "+f"(c[3])
        : "r"(a[0]), "r"(a[1]), "r"(a[2]), "r"(a[3]), "r"(b[0]), "r"(b[1]));
}

__device__ __forceinline__ void cp16(uint32_t s, const void* g) {
    asm volatile("cp.async.cg.shared.global [%0], [%1], 16;" :: "r"(s), "l"(g));
}

// One stage: Ah/Al 64 rows x 64B, Bh/Bl 128 rows x 64B. XOR swizzle c^=(r>>1)&3.
__device__ __forceinline__ void cp_stage(
    uint32_t smStage, const char* aH, const char* aL, const char* bH, const char* bL,
    int ktBytes, int tid)
{
    {   // A: thread t -> row t>>2, chunk t&3 (one per tile)
        const int r = tid >> 2, c = tid & 3;
        const int sw = (r >> 1) & 3;
        const size_t goff = ((size_t)r << 11) + (size_t)ktBytes + (c << 4);
        const uint32_t soff = r * 64 + ((c ^ sw) << 4);
        cp16(smStage + OFF_AH + soff, aH + goff);
        cp16(smStage + OFF_AL + soff, aL + goff);
    }
    {   // B: thread t -> row t>>1, chunks (t&1)*2, +1 (two per tile)
        const int r = tid >> 1;
        const int sw = (r >> 1) & 3;
#pragma unroll
        for (int cc = 0; cc < 2; cc++) {
            const int c = (tid & 1) * 2 + cc;
            const size_t goff = ((size_t)r << 11) + (size_t)ktBytes + (c << 4);
            const uint32_t soff = r * 64 + ((c ^ sw) << 4);
            cp16(smStage + OFF_BH + soff, bH + goff);
            cp16(smStage + OFF_BL + soff, bL + goff);
        }
    }
    asm volatile("cp.async.commit_group;");
}

__global__ __launch_bounds__(256, 3) void mm_kernel(
    const __nv_bfloat16* __restrict__ Ah, const __nv_bfloat16* __restrict__ Al,
    const __nv_bfloat16* __restrict__ Bth0, const __nv_bfloat16* __restrict__ Btl0,
    const __nv_bfloat16* __restrict__ Bth1, const __nv_bfloat16* __restrict__ Btl1,
    const __nv_bfloat16* __restrict__ Bth2, const __nv_bfloat16* __restrict__ Btl2,
    float* __restrict__ C0, float* __restrict__ C1, float* __restrict__ C2,
    const float* __restrict__ bias)
{
    extern __shared__ char sm[];
    uint32_t smbase;
    asm("{ .reg .u64 t; cvta.to.shared.u64 t, %1; cvt.u32.u64 %0, t; }"
        : "=r"(smbase) : "l"(sm));

    const int tid = threadIdx.x;
    const int warp = tid >> 5, lane = tid & 31;
    const int g = lane >> 2, tg = lane & 3;
    const int z = blockIdx.z;
    const __nv_bfloat16* Bth = (z == 0) ? Bth0 : (z == 1) ? Bth1 : Bth2;
    const __nv_bfloat16* Btl = (z == 0) ? Btl0 : (z == 1) ? Btl1 : Btl2;
    float* C = (z == 0) ? C0 : (z == 1) ? C1 : C2;

    const int rowBase = blockIdx.y * 64;
    const int colBase = blockIdx.x * 128;
    const int warpRow = (warp & 1) * 32;       // 2 warp-rows of 32
    const int warpCol = (warp >> 1) * 32;      // 4 warp-cols of 32

    const char* aHp = (const char*)Ah  + ((size_t)rowBase << 11);
    const char* aLp = (const char*)Al  + ((size_t)rowBase << 11);
    const char* bHp = (const char*)Bth + ((size_t)colBase << 11);
    const char* bLp = (const char*)Btl + ((size_t)colBase << 11);

    const uint32_t sig = (uint32_t)(g & 6) << 3;
    const uint32_t kp[2][2] = { { (0u ^ sig),  (16u ^ sig) },
                                { (32u ^ sig), (48u ^ sig) } };
    uint32_t aBase[2], bBase[4];
#pragma unroll
    for (int mi = 0; mi < 2; mi++)
        aBase[mi] = (uint32_t)((warpRow + mi * 16 + g) * 64 + tg * 4);
#pragma unroll
    for (int ni = 0; ni < 4; ni++)
        bBase[ni] = (uint32_t)(OFF_BH + (warpCol + ni * 8 + g) * 64 + tg * 4);

    float acc[2][4][4];
#pragma unroll
    for (int mi = 0; mi < 2; mi++)
#pragma unroll
        for (int ni = 0; ni < 4; ni++)
#pragma unroll
            for (int e = 0; e < 4; e++) acc[mi][ni][e] = 0.f;

    cp_stage(smbase + 0 * MM_STAGE, aHp, aLp, bHp, bLp, 0,  tid);
    cp_stage(smbase + 1 * MM_STAGE, aHp, aLp, bHp, bLp, 64, tid);

    int buf = 0;
    for (int it = 0; it < 32; it++) {
        if (it == 31) asm volatile("cp.async.wait_group 0;" ::: "memory");
        else          asm volatile("cp.async.wait_group 1;" ::: "memory");
        __syncthreads();
        if (it + 2 < 32) {
            int nb = buf + 2; if (nb >= 3) nb -= 3;
            cp_stage(smbase + nb * MM_STAGE, aHp, aLp, bHp, bLp, (it + 2) * 64, tid);
        }
        const uint32_t so = smbase + buf * MM_STAGE;
        if (++buf == 3) buf = 0;

#pragma unroll
        for (int ks = 0; ks < 2; ks++) {
            const uint32_t k0 = kp[ks][0], k1 = kp[ks][1];
            uint32_t ahf[2][4];
#pragma unroll
            for (int mi = 0; mi < 2; mi++) {
                const uint32_t p0 = so + aBase[mi];
                ahf[mi][0] = *(const uint32_t*)__cvta_shared_to_generic(p0 + k0);
                ahf[mi][1] = *(const uint32_t*)__cvta_shared_to_generic(p0 + k0 + 512);
                ahf[mi][2] = *(const uint32_t*)__cvta_shared_to_generic(p0 + k1);
                ahf[mi][3] = *(const uint32_t*)__cvta_shared_to_generic(p0 + k1 + 512);
            }
            uint32_t bhf[4][2];
#pragma unroll
            for (int ni = 0; ni < 4; ni++) {
                const uint32_t p0 = so + bBase[ni];
                bhf[ni][0] = *(const uint32_t*)__cvta_shared_to_generic(p0 + k0);
                bhf[ni][1] = *(const uint32_t*)__cvta_shared_to_generic(p0 + k1);
            }
            // pass 1: Ah * Bh
#pragma unroll
            for (int mi = 0; mi < 2; mi++)
#pragma unroll
                for (int ni = 0; ni < 4; ni++)
                    mma_bf16(acc[mi][ni], ahf[mi], bhf[ni]);
            // pass 2: Al * Bh
            {
                uint32_t alf[2][4];
#pragma unroll
                for (int mi = 0; mi < 2; mi++) {
                    const uint32_t p0 = so + aBase[mi] + (OFF_AL - OFF_AH);
                    alf[mi][0] = *(const uint32_t*)__cvta_shared_to_generic(p0 + k0);
                    alf[mi][1] = *(const uint32_t*)__cvta_shared_to_generic(p0 + k0 + 512);
                    alf[mi][2] = *(const uint32_t*)__cvta_shared_to_generic(p0 + k1);
                    alf[mi][3] = *(const uint32_t*)__cvta_shared_to_generic(p0 + k1 + 512);
                }
#pragma unroll
                for (int mi = 0; mi < 2; mi++)
#pragma unroll
                    for (int ni = 0; ni < 4; ni++)
                        mma_bf16(acc[mi][ni], alf[mi], bhf[ni]);
            }
            // pass 3: Ah * Bl
            {
                uint32_t blf[4][2];
#pragma unroll
                for (int ni = 0; ni < 4; ni++) {
                    const uint32_t p0 = so + bBase[ni] + (OFF_BL - OFF_BH);
                    blf[ni][0] = *(const uint32_t*)__cvta_shared_to_generic(p0 + k0);
                    blf[ni][1] = *(const uint32_t*)__cvta_shared_to_generic(p0 + k1);
                }
#pragma unroll
                for (int mi = 0; mi < 2; mi++)
#pragma unroll
                    for (int ni = 0; ni < 4; ni++)
                        mma_bf16(acc[mi][ni], ahf[mi], blf[ni]);
            }
        }
    }

    // epilogue: direct float2 stores
#pragma unroll
    for (int mi = 0; mi < 2; mi++) {
        const int row0 = rowBase + warpRow + mi * 16 + g;
#pragma unroll
        for (int ni = 0; ni < 4; ni++) {
            const int col = colBase + warpCol + ni * 8 + tg * 2;
            float b0 = 0.f, b1 = 0.f;
            if (bias) { b0 = bias[col]; b1 = bias[col + 1]; }
            float2 v0 = make_float2(acc[mi][ni][0] + b0, acc[mi][ni][1] + b1);
            float2 v1 = make_float2(acc[mi][ni][2] + b0, acc[mi][ni][3] + b1);
            *reinterpret_cast<float2*>(&C[(size_t)row0 * DM + col]) = v0;
            *reinterpret_cast<float2*>(&C[(size_t)(row0 + 8) * DM + col]) = v1;
        }
    }
}

// ---------------------------------------------------------------------------
// beta = sigmoid(x @ Wg)
// ---------------------------------------------------------------------------
__global__ __launch_bounds__(512) void beta_kernel(
    const float* __restrict__ x, const float* __restrict__ Wg,
    float* __restrict__ beta)
{
    __shared__ float xs[DM];
    const int b = blockIdx.x;
    for (int i = threadIdx.x; i < DM; i += 512) xs[i] = x[(size_t)b * DM + i];
    __syncthreads();
    const int w = threadIdx.x >> 5, lane = threadIdx.x & 31;
    float s = 0.f;
    for (int j = lane; j < DM; j += 32) s = fmaf(xs[j], Wg[(size_t)j * HEADS + w], s);
#pragma unroll
    for (int off = 16; off; off >>= 1) s += __shfl_xor_sync(0xffffffffu, s, off);
    if (lane == 0) beta[b * HEADS + w] = 1.f / (1.f + expf(-s));
}

// ---------------------------------------------------------------------------
// fast-weight delta rule, one 64-thread CTA per (b,h).
// W kept in registers for the NW write (no LDS in epilogue).
// ---------------------------------------------------------------------------
__global__ __launch_bounds__(64) void fastweight_kernel(
    const float* __restrict__ weights,
    const float* __restrict__ q, const float* __restrict__ k,
    const float* __restrict__ v, const float* __restrict__ beta,
    float* __restrict__ nw,
    __nv_bfloat16* __restrict__ ohh, __nv_bfloat16* __restrict__ ohl)
{
    __shared__ float Wsh[DK][DK + 1];
    __shared__ float ksh[DK], qsh[DK], dsh[DK];

    const int bh = blockIdx.x;
    const int b = bh >> 4, h = bh & 15;
    const int t = threadIdx.x;

    // thread t loads rows (t>>4)+4i, cols 4(t&15)..+3  -> keep in regs
    float4 wreg[16];
    const float4* W4 = reinterpret_cast<const float4*>(weights + (size_t)bh * (DK * DK));
#pragma unroll
    for (int i = 0; i < 16; i++) {
        int id = t + i * 64;
        float4 wv = W4[id];
        wreg[i] = wv;
        int e = id << 2;
        int r = e >> 6, c = e & 63;
        Wsh[r][c + 0] = wv.x; Wsh[r][c + 1] = wv.y;
        Wsh[r][c + 2] = wv.z; Wsh[r][c + 3] = wv.w;
    }
    const size_t base = (size_t)b * DM + (size_t)h * DK;
    const float kval = k[base + t];
    const float qval = q[base + t];
    const float vval = v[base + t];
    ksh[t] = kval; qsh[t] = qval;
    const float betav = beta[bh];
    __syncthreads();

    float s = 0.f;
#pragma unroll
    for (int j = 0; j < DK; j++) s = fmaf(Wsh[t][j], ksh[j], s);
    const float dv = betav * (vval - s);
    dsh[t] = dv;
    __syncthreads();

    float s2 = 0.f, kq = 0.f;
#pragma unroll
    for (int j = 0; j < DK; j++) {
        s2 = fmaf(Wsh[t][j], qsh[j], s2);
        kq = fmaf(ksh[j], qsh[j], kq);
    }
    const float o = s2 + dv * kq;
    const __nv_bfloat16 oh = __float2bfloat16_rn(o);
    ohh[base + t] = oh;
    ohl[base + t] = __float2bfloat16_rn(o - __bfloat162float(oh));

    // NW write from registers: thread t owns rows (t>>4)+4i, cols 4(t&15)
    float* NW = nw + (size_t)bh * (DK * DK);
    const int r0 = t >> 4, c4 = (t & 15) << 2;
    float4 k4;
    k4.x = ksh[c4 + 0]; k4.y = ksh[c4 + 1]; k4.z = ksh[c4 + 2]; k4.w = ksh[c4 + 3];
#pragma unroll
    for (int i = 0; i < 16; i++) {
        const int row = r0 + i * 4;
        const float d = dsh[row];
        float4 o4;
        o4.x = wreg[i].x + d * k4.x;
        o4.y = wreg[i].y + d * k4.y;
        o4.z = wreg[i].z + d * k4.z;
        o4.w = wreg[i].w + d * k4.w;
        *reinterpret_cast<float4*>(&NW[row * DK + c4]) = o4;
    }
}

// ---------------------------------------------------------------------------
extern "C" void kernel_launch(void* const* d_in, const int* in_sizes, int n_in,
                              void* d_out, int out_size)
{
    const float* x       = (const float*)d_in[0];
    const float* weights = (const float*)d_in[1];
    const float* Wq      = (const float*)d_in[2];
    const float* Wk      = (const float*)d_in[3];
    const float* Wv      = (const float*)d_in[4];
    const float* Wg      = (const float*)d_in[5];
    const float* Wo      = (const float*)d_in[6];
    const float* bo      = (const float*)d_in[7];

    float* out = (float*)d_out;
    float* nw  = out + (size_t)BATCHN * DM;

    float *qb, *bb;
    __nv_bfloat16 *xh, *xl, *wth, *wtl, *ohh, *ohl;
    cudaGetSymbolAddress((void**)&qb,  g_qkv);
    cudaGetSymbolAddress((void**)&bb,  g_beta);
    cudaGetSymbolAddress((void**)&xh,  g_xh);
    cudaGetSymbolAddress((void**)&xl,  g_xl);
    cudaGetSymbolAddress((void**)&wth, g_wth);
    cudaGetSymbolAddress((void**)&wtl, g_wtl);
    cudaGetSymbolAddress((void**)&ohh, g_ohh);
    cudaGetSymbolAddress((void**)&ohl, g_ohl);
    float* kb = qb + (size_t)BATCHN * DM;
    float* vb = kb + (size_t)BATCHN * DM;

    cudaFuncSetAttribute(mm_kernel, cudaFuncAttributeMaxDynamicSharedMemorySize, MM_SMEM);

    const size_t MS = (size_t)DM * DM;

    // 1) transpose + bf16-split the four big weight matrices
    transsplit_kernel<<<dim3(32, 32, 4), 256>>>(Wq, Wk, Wv, Wo, wth, wtl);
    // 2) split x
    split_kernel<<<1024, 256>>>(x, xh, xl);
    // 3) gate
    beta_kernel<<<BATCHN, 512>>>(x, Wg, bb);
    // 4) QKV projections (fused, grid.z = 3): 64x128 tiles -> 384 CTAs
    mm_kernel<<<dim3(8, 16, 3), 256, MM_SMEM>>>(
        xh, xl,
        wth + 0 * MS, wtl + 0 * MS,
        wth + 1 * MS, wtl + 1 * MS,
        wth + 2 * MS, wtl + 2 * MS,
        qb, kb, vb, nullptr);
    // 5) fast-weight update + read (nw -> d_out, outh pre-split bf16)
    fastweight_kernel<<<BATCHN * HEADS, 64>>>(weights, qb, kb, vb, bb, nw, ohh, ohl);
    // 6) output projection + bias
    mm_kernel<<<dim3(8, 16, 1), 256, MM_SMEM>>>(
        ohh, ohl,
        wth + 3 * MS, wtl + 3 * MS,
        wth + 3 * MS, wtl + 3 * MS,
        wth + 3 * MS, wtl + 3 * MS,
        out, out, out, bo);
}

// round 8
// speedup vs baseline: 1.5053x; 1.1736x over previous
#include <cuda_runtime.h>
#include <cuda_fp16.h>
#include <cstdint>
#include <math.h>

#define DM     1024
#define BATCHN 1024
#define HEADS  16
#define DK     64

// ---------------- scratch (no allocation allowed) ----------------
__device__ float g_qkv[3u * BATCHN * DM];            // q | k | v fp32
__device__ float g_beta[BATCHN * HEADS];
__device__ __half g_xh[BATCHN * DM];                 // x split hi (fp16)
__device__ __half g_xl[BATCHN * DM];                 // x split lo (fp16)
__device__ __half g_wt[4u * DM * DM];                // W^T fp16: Wq,Wk,Wv,Wo
__device__ __half g_ohh[BATCHN * DM];                // outh split hi
__device__ __half g_ohl[BATCHN * DM];                // outh split lo

// ---------------------------------------------------------------------------
// split fp32 -> fp16 hi/lo
// ---------------------------------------------------------------------------
__global__ __launch_bounds__(256) void split_kernel(
    const float* __restrict__ in, __half* __restrict__ hi, __half* __restrict__ lo)
{
    int idx = blockIdx.x * 256 + threadIdx.x;   // float4 index
    float4 v = reinterpret_cast<const float4*>(in)[idx];
    float f[4] = {v.x, v.y, v.z, v.w};
    __half h[4], l[4];
#pragma unroll
    for (int i = 0; i < 4; i++) {
        h[i] = __float2half_rn(f[i]);
        l[i] = __float2half_rn(f[i] - __half2float(h[i]));
    }
    __half2* h2 = reinterpret_cast<__half2*>(hi);
    __half2* l2 = reinterpret_cast<__half2*>(lo);
    h2[idx * 2 + 0] = __half2(h[0], h[1]);
    h2[idx * 2 + 1] = __half2(h[2], h[3]);
    l2[idx * 2 + 0] = __half2(l[0], l[1]);
    l2[idx * 2 + 1] = __half2(l[2], l[3]);
}

// ---------------------------------------------------------------------------
// transpose + fp16: W[K][N] -> Wt[N][K] fp16. z selects matrix.
// ---------------------------------------------------------------------------
__global__ __launch_bounds__(256) void transhalf_kernel(
    const float* __restrict__ W0, const float* __restrict__ W1,
    const float* __restrict__ W2, const float* __restrict__ W3,
    __half* __restrict__ H)
{
    __shared__ float tile[32][33];
    const int z = blockIdx.z;
    const float* W = (z == 0) ? W0 : (z == 1) ? W1 : (z == 2) ? W2 : W3;
    __half* Ht = H + (size_t)z * DM * DM;
    const int tx = threadIdx.x & 31, ty = threadIdx.x >> 5;
    const int nb = blockIdx.x * 32, kb = blockIdx.y * 32;
#pragma unroll
    for (int i = 0; i < 4; i++) {
        int k = kb + ty + i * 8;
        tile[ty + i * 8][tx] = W[(size_t)k * DM + nb + tx];
    }
    __syncthreads();
#pragma unroll
    for (int i = 0; i < 4; i++) {
        int n = nb + ty + i * 8;
        Ht[(size_t)n * DM + kb + tx] = __float2half_rn(tile[tx][ty + i * 8]);
    }
}

// ---------------------------------------------------------------------------
// fp16 2-pass GEMM on mma.sync: C = Ah*Bh + Al*Bh  (A split, B plain fp16).
// CTA tile 64x128, BK=32, 8 warps (2x4), warp tile 32x32.
// 3-stage cp.async pipeline, XOR-swizzled 64B rows, one barrier / iteration.
// ---------------------------------------------------------------------------
#define OFF_AH    0
#define OFF_AL    4096
#define OFF_BH    8192
#define MM_STAGE  16384                 // Ah(4K) | Al(4K) | Bh(8K)
#define MM_SMEM   (3 * MM_STAGE)        // 49152

__device__ __forceinline__ void mma_f16(float* c, const uint32_t* a, const uint32_t* b) {
    asm volatile(
        "mma.sync.aligned.m16n8k16.row.col.f32.f16.f16.f32 "
        "{%0,%1,%2,%3}, {%4,%5,%6,%7}, {%8,%9}, {%0,%1,%2,%3};"
        : "+f"(c[0]), "+f"(c[1]), "+f"(c[2]), "+f"(c[3])
        : "r"(a[0]), "r"(a[1]), "r"(a[2]), "r"(a[3]), "r"(b[0]), "r"(b[1]));
}

__device__ __forceinline__ void cp16(uint32_t s, const void* g) {
    asm volatile("cp.async.cg.shared.global [%0], [%1], 16;" :: "r"(s), "l"(g));
}

// One stage: Ah/Al 64 rows x 64B, Bh 128 rows x 64B. XOR swizzle c^=(r>>1)&3.
__device__ __forceinline__ void cp_stage(
    uint32_t smStage, const char* aH, const char* aL, const char* bH,
    int ktBytes, int tid)
{
    {   // A: thread t -> row t>>2, chunk t&3
        const int r = tid >> 2, c = tid & 3;
        const int sw = (r >> 1) & 3;
        const size_t goff = ((size_t)r << 11) + (size_t)ktBytes + (c << 4);
        const uint32_t soff = r * 64 + ((c ^ sw) << 4);
        cp16(smStage + OFF_AH + soff, aH + goff);
        cp16(smStage + OFF_AL + soff, aL + goff);
    }
    {   // B: thread t -> row t>>1, chunks (t&1)*2, +1
        const int r = tid >> 1;
        const int sw = (r >> 1) & 3;
#pragma unroll
        for (int cc = 0; cc < 2; cc++) {
            const int c = (tid & 1) * 2 + cc;
            const size_t goff = ((size_t)r << 11) + (size_t)ktBytes + (c << 4);
            const uint32_t soff = r * 64 + ((c ^ sw) << 4);
            cp16(smStage + OFF_BH + soff, bH + goff);
        }
    }
    asm volatile("cp.async.commit_group;");
}

__global__ __launch_bounds__(256, 3) void mm_kernel(
    const __half* __restrict__ Ah, const __half* __restrict__ Al,
    const __half* __restrict__ Bt0, const __half* __restrict__ Bt1,
    const __half* __restrict__ Bt2,
    float* __restrict__ C0, float* __restrict__ C1, float* __restrict__ C2,
    const float* __restrict__ bias)
{
    extern __shared__ char sm[];
    uint32_t smbase;
    asm("{ .reg .u64 t; cvta.to.shared.u64 t, %1; cvt.u32.u64 %0, t; }"
        : "=r"(smbase) : "l"(sm));

    const int tid = threadIdx.x;
    const int warp = tid >> 5, lane = tid & 31;
    const int g = lane >> 2, tg = lane & 3;
    const int z = blockIdx.z;
    const __half* Bt = (z == 0) ? Bt0 : (z == 1) ? Bt1 : Bt2;
    float* C = (z == 0) ? C0 : (z == 1) ? C1 : C2;

    const int rowBase = blockIdx.y * 64;
    const int colBase = blockIdx.x * 128;
    const int warpRow = (warp & 1) * 32;       // 2 warp-rows of 32
    const int warpCol = (warp >> 1) * 32;      // 4 warp-cols of 32

    const char* aHp = (const char*)Ah + ((size_t)rowBase << 11);
    const char* aLp = (const char*)Al + ((size_t)rowBase << 11);
    const char* bHp = (const char*)Bt + ((size_t)colBase << 11);

    const uint32_t sig = (uint32_t)(g & 6) << 3;
    const uint32_t kp[2][2] = { { (0u ^ sig),  (16u ^ sig) },
                                { (32u ^ sig), (48u ^ sig) } };
    uint32_t aBase[2], bBase[4];
#pragma unroll
    for (int mi = 0; mi < 2; mi++)
        aBase[mi] = (uint32_t)((warpRow + mi * 16 + g) * 64 + tg * 4);
#pragma unroll
    for (int ni = 0; ni < 4; ni++)
        bBase[ni] = (uint32_t)(OFF_BH + (warpCol + ni * 8 + g) * 64 + tg * 4);

    float acc[2][4][4];
#pragma unroll
    for (int mi = 0; mi < 2; mi++)
#pragma unroll
        for (int ni = 0; ni < 4; ni++)
#pragma unroll
            for (int e = 0; e < 4; e++) acc[mi][ni][e] = 0.f;

    cp_stage(smbase + 0 * MM_STAGE, aHp, aLp, bHp, 0,  tid);
    cp_stage(smbase + 1 * MM_STAGE, aHp, aLp, bHp, 64, tid);

    int buf = 0;
    for (int it = 0; it < 32; it++) {
        if (it == 31) asm volatile("cp.async.wait_group 0;" ::: "memory");
        else          asm volatile("cp.async.wait_group 1;" ::: "memory");
        __syncthreads();
        if (it + 2 < 32) {
            int nb = buf + 2; if (nb >= 3) nb -= 3;
            cp_stage(smbase + nb * MM_STAGE, aHp, aLp, bHp, (it + 2) * 64, tid);
        }
        const uint32_t so = smbase + buf * MM_STAGE;
        if (++buf == 3) buf = 0;

#pragma unroll
        for (int ks = 0; ks < 2; ks++) {
            const uint32_t k0 = kp[ks][0], k1 = kp[ks][1];
            uint32_t ahf[2][4];
#pragma unroll
            for (int mi = 0; mi < 2; mi++) {
                const uint32_t p0 = so + aBase[mi];
                ahf[mi][0] = *(const uint32_t*)__cvta_shared_to_generic(p0 + k0);
                ahf[mi][1] = *(const uint32_t*)__cvta_shared_to_generic(p0 + k0 + 512);
                ahf[mi][2] = *(const uint32_t*)__cvta_shared_to_generic(p0 + k1);
                ahf[mi][3] = *(const uint32_t*)__cvta_shared_to_generic(p0 + k1 + 512);
            }
            uint32_t bhf[4][2];
#pragma unroll
            for (int ni = 0; ni < 4; ni++) {
                const uint32_t p0 = so + bBase[ni];
                bhf[ni][0] = *(const uint32_t*)__cvta_shared_to_generic(p0 + k0);
                bhf[ni][1] = *(const uint32_t*)__cvta_shared_to_generic(p0 + k1);
            }
            // pass 1: Ah * Bh
#pragma unroll
            for (int mi = 0; mi < 2; mi++)
#pragma unroll
                for (int ni = 0; ni < 4; ni++)
                    mma_f16(acc[mi][ni], ahf[mi], bhf[ni]);
            // pass 2: Al * Bh
            {
                uint32_t alf[2][4];
#pragma unroll
                for (int mi = 0; mi < 2; mi++) {
                    const uint32_t p0 = so + aBase[mi] + (OFF_AL - OFF_AH);
                    alf[mi][0] = *(const uint32_t*)__cvta_shared_to_generic(p0 + k0);
                    alf[mi][1] = *(const uint32_t*)__cvta_shared_to_generic(p0 + k0 + 512);
                    alf[mi][2] = *(const uint32_t*)__cvta_shared_to_generic(p0 + k1);
                    alf[mi][3] = *(const uint32_t*)__cvta_shared_to_generic(p0 + k1 + 512);
                }
#pragma unroll
                for (int mi = 0; mi < 2; mi++)
#pragma unroll
                    for (int ni = 0; ni < 4; ni++)
                        mma_f16(acc[mi][ni], alf[mi], bhf[ni]);
            }
        }
    }

    // epilogue
#pragma unroll
    for (int mi = 0; mi < 2; mi++) {
        const int row0 = rowBase + warpRow + mi * 16 + g;
#pragma unroll
        for (int ni = 0; ni < 4; ni++) {
            const int col = colBase + warpCol + ni * 8 + tg * 2;
            float b0 = 0.f, b1 = 0.f;
            if (bias) { b0 = bias[col]; b1 = bias[col + 1]; }
            float2 v0 = make_float2(acc[mi][ni][0] + b0, acc[mi][ni][1] + b1);
            float2 v1 = make_float2(acc[mi][ni][2] + b0, acc[mi][ni][3] + b1);
            *reinterpret_cast<float2*>(&C[(size_t)row0 * DM + col]) = v0;
            *reinterpret_cast<float2*>(&C[(size_t)(row0 + 8) * DM + col]) = v1;
        }
    }
}

// ---------------------------------------------------------------------------
// beta = sigmoid(x @ Wg)
// ---------------------------------------------------------------------------
__global__ __launch_bounds__(512) void beta_kernel(
    const float* __restrict__ x, const float* __restrict__ Wg,
    float* __restrict__ beta)
{
    __shared__ float xs[DM];
    const int b = blockIdx.x;
    for (int i = threadIdx.x; i < DM; i += 512) xs[i] = x[(size_t)b * DM + i];
    __syncthreads();
    const int w = threadIdx.x >> 5, lane = threadIdx.x & 31;
    float s = 0.f;
    for (int j = lane; j < DM; j += 32) s = fmaf(xs[j], Wg[(size_t)j * HEADS + w], s);
#pragma unroll
    for (int off = 16; off; off >>= 1) s += __shfl_xor_sync(0xffffffffu, s, off);
    if (lane == 0) beta[b * HEADS + w] = 1.f / (1.f + expf(-s));
}

// ---------------------------------------------------------------------------
// fast-weight delta rule, one 64-thread CTA per (b,h).
// W kept in registers for the NW write; outh emitted pre-split fp16.
// ---------------------------------------------------------------------------
__global__ __launch_bounds__(64) void fastweight_kernel(
    const float* __restrict__ weights,
    const float* __restrict__ q, const float* __restrict__ k,
    const float* __restrict__ v, const float* __restrict__ beta,
    float* __restrict__ nw,
    __half* __restrict__ ohh, __half* __restrict__ ohl)
{
    __shared__ float Wsh[DK][DK + 1];
    __shared__ float ksh[DK], qsh[DK], dsh[DK];

    const int bh = blockIdx.x;
    const int b = bh >> 4, h = bh & 15;
    const int t = threadIdx.x;

    float4 wreg[16];
    const float4* W4 = reinterpret_cast<const float4*>(weights + (size_t)bh * (DK * DK));
#pragma unroll
    for (int i = 0; i < 16; i++) {
        int id = t + i * 64;
        float4 wv = W4[id];
        wreg[i] = wv;
        int e = id << 2;
        int r = e >> 6, c = e & 63;
        Wsh[r][c + 0] = wv.x; Wsh[r][c + 1] = wv.y;
        Wsh[r][c + 2] = wv.z; Wsh[r][c + 3] = wv.w;
    }
    const size_t base = (size_t)b * DM + (size_t)h * DK;
    const float kval = k[base + t];
    const float qval = q[base + t];
    const float vval = v[base + t];
    ksh[t] = kval; qsh[t] = qval;
    const float betav = beta[bh];
    __syncthreads();

    float s = 0.f;
#pragma unroll
    for (int j = 0; j < DK; j++) s = fmaf(Wsh[t][j], ksh[j], s);
    const float dv = betav * (vval - s);
    dsh[t] = dv;
    __syncthreads();

    float s2 = 0.f, kq = 0.f;
#pragma unroll
    for (int j = 0; j < DK; j++) {
        s2 = fmaf(Wsh[t][j], qsh[j], s2);
        kq = fmaf(ksh[j], qsh[j], kq);
    }
    const float o = s2 + dv * kq;
    const __half oh = __float2half_rn(o);
    ohh[base + t] = oh;
    ohl[base + t] = __float2half_rn(o - __half2float(oh));

    float* NW = nw + (size_t)bh * (DK * DK);
    const int r0 = t >> 4, c4 = (t & 15) << 2;
    float4 k4;
    k4.x = ksh[c4 + 0]; k4.y = ksh[c4 + 1]; k4.z = ksh[c4 + 2]; k4.w = ksh[c4 + 3];
#pragma unroll
    for (int i = 0; i < 16; i++) {
        const int row = r0 + i * 4;
        const float d = dsh[row];
        float4 o4;
        o4.x = wreg[i].x + d * k4.x;
        o4.y = wreg[i].y + d * k4.y;
        o4.z = wreg[i].z + d * k4.z;
        o4.w = wreg[i].w + d * k4.w;
        *reinterpret_cast<float4*>(&NW[row * DK + c4]) = o4;
    }
}

// ---------------------------------------------------------------------------
extern "C" void kernel_launch(void* const* d_in, const int* in_sizes, int n_in,
                              void* d_out, int out_size)
{
    const float* x       = (const float*)d_in[0];
    const float* weights = (const float*)d_in[1];
    const float* Wq      = (const float*)d_in[2];
    const float* Wk      = (const float*)d_in[3];
    const float* Wv      = (const float*)d_in[4];
    const float* Wg      = (const float*)d_in[5];
    const float* Wo      = (const float*)d_in[6];
    const float* bo      = (const float*)d_in[7];

    float* out = (float*)d_out;
    float* nw  = out + (size_t)BATCHN * DM;

    float *qb, *bb;
    __half *xh, *xl, *wt, *ohh, *ohl;
    cudaGetSymbolAddress((void**)&qb,  g_qkv);
    cudaGetSymbolAddress((void**)&bb,  g_beta);
    cudaGetSymbolAddress((void**)&xh,  g_xh);
    cudaGetSymbolAddress((void**)&xl,  g_xl);
    cudaGetSymbolAddress((void**)&wt,  g_wt);
    cudaGetSymbolAddress((void**)&ohh, g_ohh);
    cudaGetSymbolAddress((void**)&ohl, g_ohl);
    float* kb = qb + (size_t)BATCHN * DM;
    float* vb = kb + (size_t)BATCHN * DM;

    cudaFuncSetAttribute(mm_kernel, cudaFuncAttributeMaxDynamicSharedMemorySize, MM_SMEM);

    const size_t MS = (size_t)DM * DM;

    // 1) transpose + fp16 the four big weight matrices
    transhalf_kernel<<<dim3(32, 32, 4), 256>>>(Wq, Wk, Wv, Wo, wt);
    // 2) split x
    split_kernel<<<1024, 256>>>(x, xh, xl);
    // 3) gate
    beta_kernel<<<BATCHN, 512>>>(x, Wg, bb);
    // 4) QKV projections (fused, grid.z = 3)
    mm_kernel<<<dim3(8, 16, 3), 256, MM_SMEM>>>(
        xh, xl,
        wt + 0 * MS, wt + 1 * MS, wt + 2 * MS,
        qb, kb, vb, nullptr);
    // 5) fast-weight update + read (nw -> d_out, outh pre-split fp16)
    fastweight_kernel<<<BATCHN * HEADS, 64>>>(weights, qb, kb, vb, bb, nw, ohh, ohl);
    // 6) output projection + bias
    mm_kernel<<<dim3(8, 16, 1), 256, MM_SMEM>>>(
        ohh, ohl,
        wt + 3 * MS, wt + 3 * MS, wt + 3 * MS,
        out, out, out, bo);
}